// round 8
// baseline (speedup 1.0000x reference)
#include <cuda_runtime.h>
#include <cstdint>

// DotPredictor: out[e] = dot(h[src[e]], h[dst[e]]), D=64 f32.
// R8: one cache line per warp-level load. 32 lanes cooperate on each edge;
// per edge: 4 warp-wide LDG.32 (2 rows x 2 x 128B half-lines, each exactly
// one L1 wavefront at the 1.0 cyc/wf cross-LDG rate instead of the 2.07
// within-LDG replay rate). Each warp batches 8 edges (32 outstanding LDG.32).
// Reduction: multi-value butterfly — 8 edge-sums reduced in 9 shfls total;
// after it, lane L holds the full sum of edge (L>>2)&7.

#define THREADS 256

__global__ __launch_bounds__(THREADS)
void dot_predictor_kernel(const float* __restrict__ hf,
                          const int* __restrict__ src,
                          const int* __restrict__ dst,
                          float* __restrict__ out,
                          int n_edges)
{
    int tid  = blockIdx.x * THREADS + threadIdx.x;
    int warp = tid >> 5;
    int lane = tid & 31;
    int base = warp * 8;               // 8 edges per warp
    if (base >= n_edges) return;

    // ---- indices (broadcast loads) ----
    int se[8], de[8];
    if (base + 7 < n_edges) {
        const int4* s4 = (const int4*)(src + base);
        const int4* d4 = (const int4*)(dst + base);
        int4 sa = __ldg(s4), sb = __ldg(s4 + 1);
        int4 da = __ldg(d4), db = __ldg(d4 + 1);
        se[0]=sa.x; se[1]=sa.y; se[2]=sa.z; se[3]=sa.w;
        se[4]=sb.x; se[5]=sb.y; se[6]=sb.z; se[7]=sb.w;
        de[0]=da.x; de[1]=da.y; de[2]=da.z; de[3]=da.w;
        de[4]=db.x; de[5]=db.y; de[6]=db.z; de[7]=db.w;
    } else {
        #pragma unroll
        for (int i = 0; i < 8; ++i) {
            int e = min(base + i, n_edges - 1);
            se[i] = __ldg(&src[e]);
            de[i] = __ldg(&dst[e]);
        }
    }

    // ---- gathers: 4 LDG.32 per edge, each warp-instr = one 128B line ----
    float p[8];
    #pragma unroll
    for (int i = 0; i < 8; ++i) {
        const float* ps = hf + (size_t)se[i] * 64;
        const float* pd = hf + (size_t)de[i] * 64;
        float s0 = __ldg(ps + lane);
        float s1 = __ldg(ps + 32 + lane);
        float d0 = __ldg(pd + lane);
        float d1 = __ldg(pd + 32 + lane);
        p[i] = s0 * d0 + s1 * d1;
    }

    // ---- multi-value butterfly reduction: 8 sums in 9 shfls ----
    // step 1 (xor 16): keep 4 of 8
    bool b4 = lane & 16;
    float q[4];
    #pragma unroll
    for (int i = 0; i < 4; ++i) {
        float give = b4 ? p[i] : p[i + 4];
        float got  = __shfl_xor_sync(0xFFFFFFFFu, give, 16);
        q[i] = (b4 ? p[i + 4] : p[i]) + got;
    }
    // step 2 (xor 8): keep 2 of 4
    bool b3 = lane & 8;
    float r[2];
    #pragma unroll
    for (int i = 0; i < 2; ++i) {
        float give = b3 ? q[i] : q[i + 2];
        float got  = __shfl_xor_sync(0xFFFFFFFFu, give, 8);
        r[i] = (b3 ? q[i + 2] : q[i]) + got;
    }
    // step 3 (xor 4): keep 1 of 2
    bool b2 = lane & 4;
    {
        float give = b2 ? r[0] : r[1];
        float got  = __shfl_xor_sync(0xFFFFFFFFu, give, 4);
        r[0] = (b2 ? r[1] : r[0]) + got;
    }
    // steps 4,5: finish sum over remaining 4 lanes
    float v = r[0];
    v += __shfl_xor_sync(0xFFFFFFFFu, v, 2);
    v += __shfl_xor_sync(0xFFFFFFFFu, v, 1);

    // lane L holds edge (L>>2)&7; lanes 0,4,...,28 store 8 consecutive floats
    int eidx = base + ((lane >> 2) & 7);
    if ((lane & 3) == 0 && eidx < n_edges) out[eidx] = v;
}

extern "C" void kernel_launch(void* const* d_in, const int* in_sizes, int n_in,
                              void* d_out, int out_size)
{
    const float* hf  = (const float*)d_in[0];  // h: [N_NODES, 64] f32
    const int*   src = (const int*)d_in[1];    // int32 [E]
    const int*   dst = (const int*)d_in[2];
    float*       out = (float*)d_out;          // [E] f32

    int n_edges = in_sizes[1];
    int n_warps = (n_edges + 7) / 8;
    long long total_threads = (long long)n_warps * 32;
    int blocks = (int)((total_threads + THREADS - 1) / THREADS);

    dot_predictor_kernel<<<blocks, THREADS>>>(hf, src, dst, out, n_edges);
}

// round 9
// speedup vs baseline: 1.0908x; 1.0908x over previous
#include <cuda_runtime.h>
#include <cstdint>

// DotPredictor: out[e] = dot(h[src[e]], h[dst[e]]), D=64 f32.
// R9: 8 lanes/edge, 4 edges/thread, ALL 16 gathers front-batched (MLP=16).
// __launch_bounds__(256, 3) relaxes the reg budget (~85) so ptxas can keep
// 16 float4 live instead of serializing into two load waves (R7's failure).

#define VEC_PER_ROW 16   // 16 float4 per 64-float row
#define THREADS 256

__device__ __forceinline__ float dot4(float4 a, float4 b) {
    return a.x*b.x + a.y*b.y + a.z*b.z + a.w*b.w;
}

__global__ __launch_bounds__(THREADS, 3)
void dot_predictor_kernel(const float4* __restrict__ h4,
                          const int4* __restrict__ src4,
                          const int4* __restrict__ dst4,
                          float4* __restrict__ out4,
                          int n_groups)
{
    int tid   = blockIdx.x * THREADS + threadIdx.x;
    int group = tid >> 3;          // 8 lanes per group; group handles 4 edges
    int lane  = tid & 7;
    if (group >= n_groups) return;

    int4 s = __ldg(&src4[group]);  // src[4g .. 4g+3], broadcast in group
    int4 d = __ldg(&dst4[group]);

    const float4* pa0 = h4 + (size_t)s.x * VEC_PER_ROW + lane;
    const float4* pb0 = h4 + (size_t)d.x * VEC_PER_ROW + lane;
    const float4* pa1 = h4 + (size_t)s.y * VEC_PER_ROW + lane;
    const float4* pb1 = h4 + (size_t)d.y * VEC_PER_ROW + lane;
    const float4* pa2 = h4 + (size_t)s.z * VEC_PER_ROW + lane;
    const float4* pb2 = h4 + (size_t)d.z * VEC_PER_ROW + lane;
    const float4* pa3 = h4 + (size_t)s.w * VEC_PER_ROW + lane;
    const float4* pb3 = h4 + (size_t)d.w * VEC_PER_ROW + lane;

    // 16 independent LDG.128, all issued before any consumer (MLP_p1 = 16)
    float4 a00 = __ldg(pa0);
    float4 a01 = __ldg(pa0 + 8);
    float4 b00 = __ldg(pb0);
    float4 b01 = __ldg(pb0 + 8);
    float4 a10 = __ldg(pa1);
    float4 a11 = __ldg(pa1 + 8);
    float4 b10 = __ldg(pb1);
    float4 b11 = __ldg(pb1 + 8);
    float4 a20 = __ldg(pa2);
    float4 a21 = __ldg(pa2 + 8);
    float4 b20 = __ldg(pb2);
    float4 b21 = __ldg(pb2 + 8);
    float4 a30 = __ldg(pa3);
    float4 a31 = __ldg(pa3 + 8);
    float4 b30 = __ldg(pb3);
    float4 b31 = __ldg(pb3 + 8);

    float p0 = dot4(a00, b00) + dot4(a01, b01);
    float p1 = dot4(a10, b10) + dot4(a11, b11);
    float p2 = dot4(a20, b20) + dot4(a21, b21);
    float p3 = dot4(a30, b30) + dot4(a31, b31);

    // Reduce within the 8-lane group (xor 4/2/1)
    p0 += __shfl_xor_sync(0xFFFFFFFFu, p0, 4);
    p1 += __shfl_xor_sync(0xFFFFFFFFu, p1, 4);
    p2 += __shfl_xor_sync(0xFFFFFFFFu, p2, 4);
    p3 += __shfl_xor_sync(0xFFFFFFFFu, p3, 4);
    p0 += __shfl_xor_sync(0xFFFFFFFFu, p0, 2);
    p1 += __shfl_xor_sync(0xFFFFFFFFu, p1, 2);
    p2 += __shfl_xor_sync(0xFFFFFFFFu, p2, 2);
    p3 += __shfl_xor_sync(0xFFFFFFFFu, p3, 2);
    p0 += __shfl_xor_sync(0xFFFFFFFFu, p0, 1);
    p1 += __shfl_xor_sync(0xFFFFFFFFu, p1, 1);
    p2 += __shfl_xor_sync(0xFFFFFFFFu, p2, 1);
    p3 += __shfl_xor_sync(0xFFFFFFFFu, p3, 1);

    if (lane == 0) {
        out4[group] = make_float4(p0, p1, p2, p3);
    }
}

extern "C" void kernel_launch(void* const* d_in, const int* in_sizes, int n_in,
                              void* d_out, int out_size)
{
    const float4* h4   = (const float4*)d_in[0];  // h: [N_NODES, 64] f32
    const int4*   src4 = (const int4*)d_in[1];    // int32 [E], read as int4
    const int4*   dst4 = (const int4*)d_in[2];
    float4*       out4 = (float4*)d_out;          // [E] f32, written as float4

    int n_edges  = in_sizes[1];
    int n_groups = n_edges / 4;    // E = 800000, divisible by 4

    long long total_threads = (long long)n_groups * 8;
    int blocks = (int)((total_threads + THREADS - 1) / THREADS);

    dot_predictor_kernel<<<blocks, THREADS>>>(h4, src4, dst4, out4, n_groups);
}

// round 10
// speedup vs baseline: 1.1842x; 1.0856x over previous
#include <cuda_runtime.h>
#include <cuda_fp16.h>
#include <cstdint>

// DotPredictor: out[e] = dot(h[src[e]], h[dst[e]]), D=64.
// R10: two-kernel scheme.
//   K1: convert h (f32, 12.8MB) -> fp16 scratch (6.4MB) once per launch.
//   K2: gather 128B fp16 rows (half the sectors of f32 rows), fp32 accumulate.
// The ~26.6us plateau is an outstanding-sector (MSHR) service wall; halving
// bytes/edge halves the wall. 8 lanes/edge -> each row is ONE LDG.128-covered
// 128B line; 2 edges/thread; float2 coalesced output.

#define THREADS 256
#define N_NODES_MAX 50000
#define D_FEAT 64

__device__ __half2 g_h16[N_NODES_MAX * (D_FEAT / 2)];   // 6.4 MB scratch

// ---- K1: f32 -> fp16 conversion (grid-stride over half2 elements) ----
__global__ __launch_bounds__(THREADS)
void convert_kernel(const float2* __restrict__ hf2, int n2)
{
    int i = blockIdx.x * THREADS + threadIdx.x;
    if (i < n2) {
        float2 v = __ldg(&hf2[i]);
        g_h16[i] = __float22half2_rn(v);
    }
}

// ---- K2: gather + dot ----
__device__ __forceinline__ float dot_u4(uint4 a, uint4 b)
{
    const __half2* pa = (const __half2*)&a;
    const __half2* pb = (const __half2*)&b;
    float acc = 0.f;
    #pragma unroll
    for (int i = 0; i < 4; ++i) {
        float2 x = __half22float2(pa[i]);
        float2 y = __half22float2(pb[i]);
        acc += x.x * y.x + x.y * y.y;
    }
    return acc;
}

__global__ __launch_bounds__(THREADS)
void dot_predictor_kernel(const int2* __restrict__ src2,
                          const int2* __restrict__ dst2,
                          float2* __restrict__ out2,
                          int n_edges)
{
    int tid  = blockIdx.x * THREADS + threadIdx.x;
    int grp  = tid >> 3;           // 8 lanes per group; group handles 2 edges
    int lane = tid & 7;
    int e0   = grp * 2;
    if (e0 >= n_edges) return;

    int2 s = __ldg(&src2[grp]);    // broadcast within the 8-lane group
    int2 d = __ldg(&dst2[grp]);

    const uint4* row_s0 = (const uint4*)(g_h16 + (size_t)s.x * 32) + lane;
    const uint4* row_d0 = (const uint4*)(g_h16 + (size_t)d.x * 32) + lane;
    const uint4* row_s1 = (const uint4*)(g_h16 + (size_t)s.y * 32) + lane;
    const uint4* row_d1 = (const uint4*)(g_h16 + (size_t)d.y * 32) + lane;

    // 4 independent LDG.128; each warp-level instr touches 4 full 128B lines
    uint4 a0 = __ldg(row_s0);
    uint4 b0 = __ldg(row_d0);
    uint4 a1 = __ldg(row_s1);
    uint4 b1 = __ldg(row_d1);

    float p0 = dot_u4(a0, b0);
    float p1 = dot_u4(a1, b1);

    // Reduce within the 8-lane group (xor 4/2/1)
    p0 += __shfl_xor_sync(0xFFFFFFFFu, p0, 4);
    p1 += __shfl_xor_sync(0xFFFFFFFFu, p1, 4);
    p0 += __shfl_xor_sync(0xFFFFFFFFu, p0, 2);
    p1 += __shfl_xor_sync(0xFFFFFFFFu, p1, 2);
    p0 += __shfl_xor_sync(0xFFFFFFFFu, p0, 1);
    p1 += __shfl_xor_sync(0xFFFFFFFFu, p1, 1);

    if (lane == 0) out2[grp] = make_float2(p0, p1);
}

extern "C" void kernel_launch(void* const* d_in, const int* in_sizes, int n_in,
                              void* d_out, int out_size)
{
    const float2* hf2  = (const float2*)d_in[0];  // h: [N,64] f32 as float2
    const int2*   src2 = (const int2*)d_in[1];    // int32 [E]
    const int2*   dst2 = (const int2*)d_in[2];
    float2*       out2 = (float2*)d_out;          // [E] f32 as float2

    int n_h     = in_sizes[0];      // N*64 floats
    int n_edges = in_sizes[1];

    // K1: convert table to fp16 scratch
    int n2 = n_h / 2;               // half2 count
    int cblocks = (n2 + THREADS - 1) / THREADS;
    convert_kernel<<<cblocks, THREADS>>>(hf2, n2);

    // K2: gather + dot (2 edges per 8-lane group)
    int n_groups = (n_edges + 1) / 2;
    long long total_threads = (long long)n_groups * 8;
    int blocks = (int)((total_threads + THREADS - 1) / THREADS);
    dot_predictor_kernel<<<blocks, THREADS>>>(src2, dst2, out2, n_edges);
}

// round 11
// speedup vs baseline: 1.4025x; 1.1843x over previous
#include <cuda_runtime.h>
#include <cuda_fp16.h>
#include <cstdint>

// DotPredictor: out[e] = dot(h[src[e]], h[dst[e]]), D=64.
// R11: fp16 table (K1 converts once), gather kernel does the dot in HFMA2:
// per 16B row-chunk pair: 2 HMUL2 + 2 HFMA2 + 2 cvt + adds (vs 8 cvt + 8 FFMA
// in R10) -> cuts the issue-bound instruction stream ~2x. Short fp16 chains
// (2 products per accumulator) keep accumulation error ~2e-4 norm-relative.

#define THREADS 256
#define N_NODES_MAX 50000
#define D_FEAT 64

__device__ __half2 g_h16[N_NODES_MAX * (D_FEAT / 2)];   // 6.4 MB scratch

// ---- K1: f32 -> fp16 conversion, float4 granularity ----
__global__ __launch_bounds__(THREADS)
void convert_kernel(const float4* __restrict__ hf4, int n4)
{
    int i = blockIdx.x * THREADS + threadIdx.x;
    if (i < n4) {
        float4 v = __ldg(&hf4[i]);
        __half2 lo = __floats2half2_rn(v.x, v.y);
        __half2 hi = __floats2half2_rn(v.z, v.w);
        g_h16[i * 2]     = lo;
        g_h16[i * 2 + 1] = hi;
    }
}

// ---- K2: gather + HFMA2 dot ----
__device__ __forceinline__ float dot_u4_h2(uint4 a, uint4 b)
{
    const __half2* pa = (const __half2*)&a;
    const __half2* pb = (const __half2*)&b;
    // two short accumulators (chain length 2) to bound fp16 rounding
    __half2 acc0 = __hmul2(pa[0], pb[0]);
    acc0 = __hfma2(pa[1], pb[1], acc0);
    __half2 acc1 = __hmul2(pa[2], pb[2]);
    acc1 = __hfma2(pa[3], pb[3], acc1);
    float2 f0 = __half22float2(acc0);
    float2 f1 = __half22float2(acc1);
    return (f0.x + f0.y) + (f1.x + f1.y);
}

__global__ __launch_bounds__(THREADS)
void dot_predictor_kernel(const int2* __restrict__ src2,
                          const int2* __restrict__ dst2,
                          float2* __restrict__ out2,
                          int n_edges)
{
    int tid  = blockIdx.x * THREADS + threadIdx.x;
    int grp  = tid >> 3;           // 8 lanes per group; group handles 2 edges
    int lane = tid & 7;
    int e0   = grp * 2;
    if (e0 >= n_edges) return;

    int2 s = __ldg(&src2[grp]);    // broadcast within the 8-lane group
    int2 d = __ldg(&dst2[grp]);

    const uint4* row_s0 = (const uint4*)(g_h16 + (size_t)s.x * 32) + lane;
    const uint4* row_d0 = (const uint4*)(g_h16 + (size_t)d.x * 32) + lane;
    const uint4* row_s1 = (const uint4*)(g_h16 + (size_t)s.y * 32) + lane;
    const uint4* row_d1 = (const uint4*)(g_h16 + (size_t)d.y * 32) + lane;

    // 4 independent LDG.128; each warp-level instr covers 4 full 128B lines
    uint4 a0 = __ldg(row_s0);
    uint4 b0 = __ldg(row_d0);
    uint4 a1 = __ldg(row_s1);
    uint4 b1 = __ldg(row_d1);

    float p0 = dot_u4_h2(a0, b0);
    float p1 = dot_u4_h2(a1, b1);

    // Reduce within the 8-lane group (xor 4/2/1)
    p0 += __shfl_xor_sync(0xFFFFFFFFu, p0, 4);
    p1 += __shfl_xor_sync(0xFFFFFFFFu, p1, 4);
    p0 += __shfl_xor_sync(0xFFFFFFFFu, p0, 2);
    p1 += __shfl_xor_sync(0xFFFFFFFFu, p1, 2);
    p0 += __shfl_xor_sync(0xFFFFFFFFu, p0, 1);
    p1 += __shfl_xor_sync(0xFFFFFFFFu, p1, 1);

    if (lane == 0) out2[grp] = make_float2(p0, p1);
}

extern "C" void kernel_launch(void* const* d_in, const int* in_sizes, int n_in,
                              void* d_out, int out_size)
{
    const float4* hf4  = (const float4*)d_in[0];  // h: [N,64] f32 as float4
    const int2*   src2 = (const int2*)d_in[1];    // int32 [E]
    const int2*   dst2 = (const int2*)d_in[2];
    float2*       out2 = (float2*)d_out;          // [E] f32 as float2

    int n_h     = in_sizes[0];      // N*64 floats
    int n_edges = in_sizes[1];

    // K1: convert table to fp16 scratch
    int n4 = n_h / 4;               // float4 count
    int cblocks = (n4 + THREADS - 1) / THREADS;
    convert_kernel<<<cblocks, THREADS>>>(hf4, n4);

    // K2: gather + dot (2 edges per 8-lane group)
    int n_groups = (n_edges + 1) / 2;
    long long total_threads = (long long)n_groups * 8;
    int blocks = (int)((total_threads + THREADS - 1) / THREADS);
    dot_predictor_kernel<<<blocks, THREADS>>>(src2, dst2, out2, n_edges);
}